// round 4
// baseline (speedup 1.0000x reference)
#include <cuda_runtime.h>
#include <cuda_bf16.h>

// Problem shape (fixed for this bench problem)
#define SEQ  1024
#define BAT  512
#define NTAG 64
#define TSTRIDE (BAT * NTAG)
#define LN2 0.69314718055994531f

typedef unsigned long long ull;

// Scratch (device globals: allocation-free rule)
__device__ float g_denom[BAT];
__device__ float g_score[BAT];
__device__ int   g_maskT[BAT * SEQ];
__device__ int   g_tags_is64;
__device__ int   g_mask_ones;

// named barrier over the 4 forward warps (threads 0..127)
#define BAR1() asm volatile("bar.sync 1, 128;" ::: "memory")

// ---------------------------------------------------------------------------
__global__ void detect_tags_kernel(const int* __restrict__ tags32) {
    int is64 = 1;
    for (int i = 1; i < 128; i += 2)
        if (tags32[i] != 0) { is64 = 0; break; }
    g_tags_is64 = is64;
    g_mask_ones = 1;
}

__device__ __forceinline__ int load_tag(const void* tags, size_t idx, int is64) {
    if (is64) return (int)((const long long*)tags)[idx];
    return ((const int*)tags)[idx];
}

// ---------------------------------------------------------------------------
__global__ void mask_transpose_kernel(const int* __restrict__ mask) {
    int idx = blockIdx.x * blockDim.x + threadIdx.x;
    if (idx < SEQ * BAT) {
        int t = idx / BAT;
        int b = idx - t * BAT;
        int v = mask[idx];
        g_maskT[b * SEQ + t] = v;
        if (v != 1) g_mask_ones = 0;   // benign race: all writers store 0
    }
}

// ---------------------------------------------------------------------------
// One linear-space forward step, column-pair split (fast path).
// Thread pair (even=rows 0-31, odd=rows 32-63) owns column c.
// Invariant: alpha_j = m0 + e_sum*ln2 + log(s_j).
// ---------------------------------------------------------------------------
__device__ __forceinline__ void fstep(
    const float* __restrict__ rd, float* __restrict__ wr,
    int c, int half, const ull* __restrict__ Ep, float rawv, int& e_sum)
{
    // per-step multiplier: c_t * renorm scale (off critical path)
    float cmul = 0.f;
    if (!half) cmul = __expf(rawv);
    const float s0 = rd[0];                       // broadcast LDS
    int ex = (__float_as_int(s0) >> 23) & 0xFF;
    ex = max(1, min(ex, 253));
    e_sum += ex - 127;
    const float rsc = __int_as_float((254 - ex) << 23);  // exact 2^(127-ex+127)

    // half-dot over 32 rows: 8 float4 loads (staggered for odd half), 16 FFMA2
    const float4* s4 = (const float4*)(rd + half * 32);
    ull a0 = 0ull, a1 = 0ull, a2 = 0ull, a3 = 0ull;
#pragma unroll
    for (int i = 0; i < 8; i += 2) {
        const int i0 = half ? ((i + 4) & 7) : i;
        const int i1 = half ? ((i + 5) & 7) : (i + 1);
        float4 sA = s4[i0];
        float4 sB = s4[i1];
        ull p0, p1, p2, p3;
        asm("mov.b64 %0, {%1, %2};" : "=l"(p0) : "f"(sA.x), "f"(sA.y));
        asm("mov.b64 %0, {%1, %2};" : "=l"(p1) : "f"(sA.z), "f"(sA.w));
        asm("mov.b64 %0, {%1, %2};" : "=l"(p2) : "f"(sB.x), "f"(sB.y));
        asm("mov.b64 %0, {%1, %2};" : "=l"(p3) : "f"(sB.z), "f"(sB.w));
        asm("fma.rn.f32x2 %0, %1, %2, %0;" : "+l"(a0) : "l"(p0), "l"(Ep[2 * i0 + 0]));
        asm("fma.rn.f32x2 %0, %1, %2, %0;" : "+l"(a1) : "l"(p1), "l"(Ep[2 * i0 + 1]));
        asm("fma.rn.f32x2 %0, %1, %2, %0;" : "+l"(a2) : "l"(p2), "l"(Ep[2 * i1 + 0]));
        asm("fma.rn.f32x2 %0, %1, %2, %0;" : "+l"(a3) : "l"(p3), "l"(Ep[2 * i1 + 1]));
    }
    asm("add.rn.f32x2 %0, %0, %1;" : "+l"(a0) : "l"(a2));
    asm("add.rn.f32x2 %0, %0, %1;" : "+l"(a1) : "l"(a3));
    asm("add.rn.f32x2 %0, %0, %1;" : "+l"(a0) : "l"(a1));
    float lo, hi;
    asm("mov.b64 {%0, %1}, %2;" : "=f"(lo), "=f"(hi) : "l"(a0));
    float partial = lo + hi;

    // combine halves within the lane pair; even lane writes the new s
    float other = __shfl_down_sync(0xffffffffu, partial, 1);
    if (!half) wr[c] = (partial + other) * (cmul * rsc);
    BAR1();
}

// ---------------------------------------------------------------------------
// Fused forward (warps 0-3) + gold-path score (warp 4). One block per batch.
// ---------------------------------------------------------------------------
__global__ __launch_bounds__(160) void crf_fused_kernel(
    const float* __restrict__ logits,   // [S, B, T]
    const void*  __restrict__ tags,     // [S, B] int32/int64 (detected)
    const float* __restrict__ trans,    // [T, T]
    const float* __restrict__ startt,   // [T]
    const float* __restrict__ endt)     // [T]
{
    const int b = blockIdx.x;
    const int tid = threadIdx.x;

    // ===================== score warp (threads 128-159) =====================
    if (tid >= 128) {
        const int lane = tid - 128;
        const int is64 = g_tags_is64;
        const int* mrow = &g_maskT[b * SEQ];
        float s = 0.f;
        int msum = 0;
        for (int t = lane; t < SEQ; t += 32) {
            const int tg = load_tag(tags, (size_t)t * BAT + b, is64);
            const int mt = mrow[t];
            msum += mt;
            if (t < SEQ - 1) {
                const int tgn = load_tag(tags, (size_t)(t + 1) * BAT + b, is64);
                const int mtn = mrow[t + 1];
                s += trans[tg * NTAG + tgn] * (float)mtn;
                s += logits[((size_t)t * BAT + b) * NTAG + tg] * (float)mt;
            }
        }
#pragma unroll
        for (int o = 16; o > 0; o >>= 1) {
            s += __shfl_xor_sync(0xffffffffu, s, o);
            msum += __shfl_xor_sync(0xffffffffu, msum, o);
        }
        if (lane == 0) {
            const int last_idx = msum - 1;
            const int last_tag = load_tag(tags, (size_t)last_idx * BAT + b, is64);
            const int tg0 = load_tag(tags, (size_t)b, is64);
            const float mlast = (float)mrow[SEQ - 1];
            g_score[b] = s + startt[tg0] + endt[last_tag]
                       + logits[((size_t)(SEQ - 1) * BAT + b) * NTAG + last_tag] * mlast;
        }
        return;  // never touches named barrier 1
    }

    // ===================== forward warps (threads 0-127) =====================
    const int w = tid >> 5;
    const int l = tid & 31;
    const int c = tid >> 1;      // column 0..63
    const int half = tid & 1;    // 0: rows 0-31, 1: rows 32-63

    __shared__ float se[2][NTAG];
    __shared__ float sh_aux[4];

    // init: alpha0 on threads 0..63 (col j = tid)
    float a0 = 0.f;
    if (tid < NTAG) {
        a0 = startt[tid] + logits[(size_t)b * NTAG + tid];
        if (tid == 0) sh_aux[0] = a0;
    }
    BAR1();
    const float m0 = sh_aux[0];
    if (tid < NTAG) se[0][tid] = __expf(a0 - m0);

    const float* lptr = logits + (size_t)b * NTAG + c;

    if (g_mask_ones) {
        // -------- FAST PATH --------
        // E half-column in packed regs: rows [half*32, half*32+32) of column c
        ull Ep[16];
#pragma unroll
        for (int i = 0; i < 16; i++) {
            float e0 = __expf(trans[(half * 32 + 2 * i) * NTAG + c]);
            float e1 = __expf(trans[(half * 32 + 2 * i + 1) * NTAG + c]);
            asm("mov.b64 %0, {%1, %2};" : "=l"(Ep[i]) : "f"(e0), "f"(e1));
        }

        // prefetch ring (even lanes only), depth 8
        float raw[8];
        if (!half) {
#pragma unroll
            for (int u = 0; u < 8; u++)
                raw[u] = lptr[(size_t)(1 + u) * TSTRIDE];
        }
        BAR1();  // se[0] visible

        int e_sum = 0;
        for (int t0 = 1; t0 + 7 <= SEQ - 1; t0 += 8) {
#pragma unroll
            for (int u = 0; u < 8; u++) {
                fstep(se[u & 1], se[(u & 1) ^ 1], c, half, Ep, raw[u], e_sum);
                if (!half && (t0 + u + 8 <= SEQ - 1))
                    raw[u] = lptr[(size_t)(t0 + u + 8) * TSTRIDE];
            }
        }
        // remainder: t = 1017..1023 (7 steps); final s lands in se[1]
#pragma unroll
        for (int u = 0; u < 7; u++)
            fstep(se[u & 1], se[(u & 1) ^ 1], c, half, Ep, raw[u], e_sum);

        // final logsumexp over columns: x_j = m0 + e_sum*ln2 + log(s_j) + end_j
        float x = -3.0e38f;
        if (tid < NTAG)
            x = m0 + (float)e_sum * LN2 + logf(se[1][tid]) + endt[tid];
        float mm = x;
#pragma unroll
        for (int o = 16; o > 0; o >>= 1)
            mm = fmaxf(mm, __shfl_xor_sync(0xffffffffu, mm, o));
        if (tid < NTAG && l == 0) sh_aux[w] = mm;   // w = 0 or 1
        BAR1();
        if (tid < NTAG) {
            mm = fmaxf(sh_aux[0], sh_aux[1]);
            float e = __expf(x - mm);
#pragma unroll
            for (int o = 16; o > 0; o >>= 1)
                e += __shfl_xor_sync(0xffffffffu, e, o);
            if (l == 0) sh_aux[2 + w] = e;
        }
        BAR1();
        if (tid == 0)
            g_denom[b] = fmaxf(sh_aux[0], sh_aux[1]) + logf(sh_aux[2] + sh_aux[3]);
        return;
    }

    // -------- GENERAL PATH (mask not all ones): log-space, threads 0-63 work --------
    {
        ull Ep[NTAG / 2];
        if (tid < NTAG) {
#pragma unroll
            for (int i = 0; i < NTAG / 2; i++) {
                float e0 = __expf(trans[(2 * i) * NTAG + tid]);
                float e1 = __expf(trans[(2 * i + 1) * NTAG + tid]);
                asm("mov.b64 %0, {%1, %2};" : "=l"(Ep[i]) : "f"(e0), "f"(e1));
            }
        }
        __shared__ float sm0[2];
        float alpha = a0;
        float m = m0;
        const int* mrow = &g_maskT[b * SEQ];
        const float* lp64 = logits + (size_t)b * NTAG + tid;
        float logit_next = (tid < NTAG) ? lp64[(size_t)1 * TSTRIDE] : 0.f;

        for (int t = 1; t < SEQ; t++) {
            const int buf = t & 1;
            const float logit = logit_next;
            if (tid < NTAG && t + 1 < SEQ) logit_next = lp64[(size_t)(t + 1) * TSTRIDE];
            const int mk = mrow[t];

            if (tid < NTAG) {
                se[buf][tid] = __expf(alpha - m);
                if (tid == 0) sm0[buf] = alpha;
            }
            BAR1();

            if (tid < NTAG) {
                ull acc0 = 0ull, acc1 = 0ull;
                const float4* s4 = (const float4*)(&se[buf][0]);
#pragma unroll
                for (int i = 0; i < NTAG / 4; i++) {
                    float4 sv = s4[i];
                    ull p0, p1;
                    asm("mov.b64 %0, {%1, %2};" : "=l"(p0) : "f"(sv.x), "f"(sv.y));
                    asm("mov.b64 %0, {%1, %2};" : "=l"(p1) : "f"(sv.z), "f"(sv.w));
                    asm("fma.rn.f32x2 %0, %1, %2, %0;" : "+l"(acc0) : "l"(p0), "l"(Ep[2 * i]));
                    asm("fma.rn.f32x2 %0, %1, %2, %0;" : "+l"(acc1) : "l"(p1), "l"(Ep[2 * i + 1]));
                }
                float q0, q1, q2, q3;
                asm("mov.b64 {%0, %1}, %2;" : "=f"(q0), "=f"(q1) : "l"(acc0));
                asm("mov.b64 {%0, %1}, %2;" : "=f"(q2), "=f"(q3) : "l"(acc1));
                const float v = (q0 + q1) + (q2 + q3);
                const float na = logit + m + __logf(v);
                alpha = mk ? na : alpha;
                m = sm0[buf];
            }
            BAR1();
        }

        float x = -3.0e38f;
        if (tid < NTAG) x = alpha + endt[tid];
        float mm = x;
#pragma unroll
        for (int o = 16; o > 0; o >>= 1)
            mm = fmaxf(mm, __shfl_xor_sync(0xffffffffu, mm, o));
        if (tid < NTAG && l == 0) sh_aux[w] = mm;
        BAR1();
        if (tid < NTAG) {
            mm = fmaxf(sh_aux[0], sh_aux[1]);
            float e = __expf(x - mm);
#pragma unroll
            for (int o = 16; o > 0; o >>= 1)
                e += __shfl_xor_sync(0xffffffffu, e, o);
            if (l == 0) sh_aux[2 + w] = e;
        }
        BAR1();
        if (tid == 0)
            g_denom[b] = fmaxf(sh_aux[0], sh_aux[1]) + logf(sh_aux[2] + sh_aux[3]);
    }
}

// ---------------------------------------------------------------------------
// Deterministic final reduction: out = sum_b (score_b - denom_b)
// ---------------------------------------------------------------------------
__global__ void crf_reduce_kernel(float* __restrict__ out) {
    __shared__ float sm[BAT];
    const int i = threadIdx.x;
    sm[i] = g_score[i] - g_denom[i];
    __syncthreads();
    for (int o = BAT / 2; o > 0; o >>= 1) {
        if (i < o) sm[i] += sm[i + o];
        __syncthreads();
    }
    if (i == 0) out[0] = sm[0];
}

// ---------------------------------------------------------------------------
extern "C" void kernel_launch(void* const* d_in, const int* in_sizes, int n_in,
                              void* d_out, int out_size) {
    const float* logits = (const float*)d_in[0];   // [S,B,T] f32
    const void*  tags   = d_in[1];                 // [S,B] i32 or i64
    const int*   mask   = (const int*)d_in[2];     // [S,B] i32
    const float* trans  = (const float*)d_in[3];   // [T,T]
    const float* startt = (const float*)d_in[4];   // [T]
    const float* endt   = (const float*)d_in[5];   // [T]
    float* out = (float*)d_out;

    detect_tags_kernel<<<1, 1>>>((const int*)tags);
    mask_transpose_kernel<<<(SEQ * BAT + 255) / 256, 256>>>(mask);
    crf_fused_kernel<<<BAT, 160>>>(logits, tags, trans, startt, endt);
    crf_reduce_kernel<<<1, BAT>>>(out);
}